// round 12
// baseline (speedup 1.0000x reference)
#include <cuda_runtime.h>
#include <cuda_fp16.h>
#include <cstdint>

// MorphLayer == conv2d(x, exp(k1)-exp(k2), VALID 3x3) + bias  (exact reduction)
// B=32 C=64 H=W=64 -> Ho=Wo=62, F=128.
// HMMA implicit-GEMM, single fp16 product, fp32 acc.
// R12: CTA 256thr/8 warps, job M=256 (4 oh x 64 w) x N=64, warp tile 64x32
// -> 192 smem bytes/MMA at 16 warps/SM and 2 CTAs/SM. SMEM: 6-slot ring slab
// (49.4KB) + 6 resident taps (48KB) + 2x8KB stream buffers for taps 6..8
// (cp.async double-buffered) = 114.9KB/CTA. Register double-buffered frags.

#define Hn  64
#define Wn  64
#define HOn 62
#define WOn 62
#define Fn  128
#define Cn  64

#define SLAB_ROWS  386                     // 6 slots * 64 + 2 overflow pad rows
#define SLAB_BYTES (SLAB_ROWS * 128)       // 49408
#define WOFF       SLAB_BYTES
#define WRES_BYTES (6 * 8192)              // taps 0..5 resident (this f-half)
#define SBUF0      (WOFF + WRES_BYTES)     // 98560
#define SBUF1      (SBUF0 + 8192)          // 106752
#define SMEM_TOTAL (SBUF1 + 8192)          // 114944 -> 2 CTAs/SM (229.9KB/SM)

#define NCTA_PER_HALF 148
#define JOBS_PER_HALF 512                  // 16 h-tiles (4 rows each) * 32 bz

// fp16 weights, SW128-swizzled: [tap][f=128][c=64]
__device__ __align__(16) unsigned char g_W[9 * 16384];

__device__ __forceinline__ uint32_t smem_u32(const void* p) {
    uint32_t a;
    asm("{ .reg .u64 t; cvta.to.shared.u64 t, %1; cvt.u32.u64 %0, t; }" : "=r"(a) : "l"(p));
    return a;
}

#define LDSM4(r, addr)                                                          \
    asm volatile("ldmatrix.sync.aligned.m8n8.x4.shared.b16 {%0,%1,%2,%3}, [%4];" \
                 : "=r"((r)[0]), "=r"((r)[1]), "=r"((r)[2]), "=r"((r)[3])        \
                 : "r"(addr))

#define MMA(d, a, b0, b1)                                                       \
    asm volatile("mma.sync.aligned.m16n8k16.row.col.f32.f16.f16.f32 "           \
                 "{%0,%1,%2,%3}, {%4,%5,%6,%7}, {%8,%9}, {%0,%1,%2,%3};"        \
                 : "+f"((d)[0]), "+f"((d)[1]), "+f"((d)[2]), "+f"((d)[3])        \
                 : "r"((a)[0]), "r"((a)[1]), "r"((a)[2]), "r"((a)[3]),           \
                   "r"(b0), "r"(b1))

// load step fragments into buffer BUF (compile-time)
#define LOAD_STEP(BUF, ABASE, SWZA, BBASE, KCB)                                 \
    do {                                                                        \
        const uint32_t _ao = ((KCB) + a_hi16) ^ (SWZA);                         \
        const uint32_t _bo = ((KCB) + b_off16) ^ swzB;                          \
        LDSM4(Af[BUF][0], (ABASE) + _ao);                                       \
        LDSM4(Af[BUF][1], (ABASE) + 2048 + _ao);                                \
        LDSM4(Af[BUF][2], (ABASE) + 4096 + _ao);                                \
        LDSM4(Af[BUF][3], (ABASE) + 6144 + _ao);                                \
        LDSM4(Bf[BUF][0], (BBASE) + _bo);                                       \
        LDSM4(Bf[BUF][1], (BBASE) + 2048 + _bo);                                \
    } while (0)

#define MMA_STEP(BUF)                                                           \
    do {                                                                        \
        _Pragma("unroll")                                                       \
        for (int mi = 0; mi < 4; mi++) {                                        \
            MMA(acc[mi][0], Af[BUF][mi], Bf[BUF][0][0], Bf[BUF][0][1]);         \
            MMA(acc[mi][1], Af[BUF][mi], Bf[BUF][0][2], Bf[BUF][0][3]);         \
            MMA(acc[mi][2], Af[BUF][mi], Bf[BUF][1][0], Bf[BUF][1][1]);         \
            MMA(acc[mi][3], Af[BUF][mi], Bf[BUF][1][2], Bf[BUF][1][3]);         \
        }                                                                       \
    } while (0)

// ---------------- weight prep ----------------
__global__ void prep_w(const float* __restrict__ k1, const float* __restrict__ k2) {
    int idx = blockIdx.x * 256 + threadIdx.x;       // 73728 = 9*128*64
    int t   = idx >> 13;
    int rem = idx & 8191;
    int f   = rem >> 6;
    int c   = rem & 63;
    int src = (t * 64 + c) * 128 + f;               // k1 layout (kh,kw,C,F)
    float w = expf(k1[src]) - expf(k2[src]);
    __half h = __float2half_rn(w);
    unsigned off = (unsigned)(f * 128 + c * 2);
    off = off ^ ((off >> 3) & 0x70);                // SW128 swizzle
    *(unsigned short*)(g_W + t * 16384 + off) = *(unsigned short*)&h;
}

// ---------------- main kernel ----------------
extern __shared__ char smem_raw[];

__device__ __forceinline__ void build_rows(const float* __restrict__ xb,
                                           char* smem, int tid,
                                           int gh0, int nrows) {
    #pragma unroll 1
    for (int it = 0; it < 2 * nrows; it++) {
        int t  = tid + it * 256;
        int gw = t & 63;
        int cg = (t >> 6) & 7;
        int gh = gh0 + (t >> 9);
        unsigned short hs[8];
        if (gh < Hn) {
            const float* xp = xb + (size_t)(cg * 8) * (Hn * Wn) + gh * Wn + gw;
            #pragma unroll
            for (int i = 0; i < 8; i++) {
                __half h = __float2half_rn(xp[(size_t)i * (Hn * Wn)]);
                hs[i] = *(unsigned short*)&h;
            }
        } else {
            #pragma unroll
            for (int i = 0; i < 8; i++) hs[i] = 0;
        }
        unsigned row  = (unsigned)((gh % 6) * 64 + gw);     // ring slot
        unsigned boff = row * 128 + cg * 16;
        unsigned sw   = boff ^ ((boff >> 3) & 0x70);
        *(uint4*)(smem + sw) =
            make_uint4((uint32_t)hs[0] | ((uint32_t)hs[1] << 16),
                       (uint32_t)hs[2] | ((uint32_t)hs[3] << 16),
                       (uint32_t)hs[4] | ((uint32_t)hs[5] << 16),
                       (uint32_t)hs[6] | ((uint32_t)hs[7] << 16));
    }
}

__device__ __forceinline__ void stream_tap(uint32_t dst, const unsigned char* src,
                                           int tid) {
    // 8KB = 512 x 16B chunks, 256 threads -> 2 each
    asm volatile("cp.async.cg.shared.global [%0], [%1], 16;"
                 :: "r"(dst + (uint32_t)tid * 16), "l"(src + tid * 16));
    asm volatile("cp.async.cg.shared.global [%0], [%1], 16;"
                 :: "r"(dst + 4096u + (uint32_t)tid * 16), "l"(src + 4096 + tid * 16));
    asm volatile("cp.async.commit_group;");
}

__global__ void __launch_bounds__(256, 2)
conv_hmma_kernel(const float* __restrict__ x,
                 const float* __restrict__ bias,
                 float* __restrict__ out) {
    const int tid  = threadIdx.x;
    const int lane = tid & 31;
    const int wid  = tid >> 5;
    const int wm   = wid & 3;          // output row within job (0..3)
    const int wn   = wid >> 2;         // f 32-block within CTA's 64
    const int fh   = blockIdx.x;       // filter half of 128
    const int cid  = blockIdx.y;

    int jstart, jcount;
    if (cid < 68) { jstart = cid * 4;              jcount = 4; }
    else          { jstart = 272 + (cid - 68) * 3; jcount = 3; }

    const uint32_t sb = smem_u32(smem_raw);

    // ---- resident weight load: taps 0..5 of this f-half (48KB) ----
    {
        const unsigned char* src = g_W + fh * 8192;
        #pragma unroll
        for (int j = 0; j < 12; j++) {
            int k = tid + j * 256;                  // 3072 chunks of 16B
            int tap = k >> 9;
            int rem = k & 511;
            asm volatile("cp.async.cg.shared.global [%0], [%1], 16;"
                         :: "r"(sb + WOFF + (uint32_t)k * 16),
                            "l"(src + (size_t)tap * 16384 + rem * 16));
        }
        asm volatile("cp.async.commit_group;");
    }

    // zero overflow pad rows 384..385 (feeds only discarded ow>=62 outputs)
    if (tid < 16) {
        *(uint4*)(smem_raw + 384 * 128 + tid * 16) = make_uint4(0u, 0u, 0u, 0u);
    }

    // lane-constant addressing
    const uint32_t a_hi16  = (uint32_t)(lane >> 4) * 16;
    const int      fb0     = wn * 32 + (lane & 7) + ((lane >> 4) & 1) * 8;
    const uint32_t b_off16 = (uint32_t)((lane >> 3) & 1) * 16;
    const uint32_t swzB    = (uint32_t)(fb0 & 7) << 4;
    const int      arow    = lane & 15;

    // per-warp streamed-tap bases (include fb0 row offset)
    const uint32_t sbuf0 = sb + SBUF0 + (uint32_t)fb0 * 128;
    const uint32_t sbuf1 = sb + SBUF1 + (uint32_t)fb0 * 128;
    const uint32_t wres  = sb + WOFF + (uint32_t)fb0 * 128;

    // streamed-tap global sources
    const unsigned char* gsrc6 = g_W + 6 * 16384 + fh * 8192;
    const unsigned char* gsrc7 = g_W + 7 * 16384 + fh * 8192;
    const unsigned char* gsrc8 = g_W + 8 * 16384 + fh * 8192;

    // bias hoisted
    float bv0[4], bv1[4];
    #pragma unroll
    for (int ni = 0; ni < 4; ni++) {
        const int f = fh * 64 + wn * 32 + ni * 8 + (lane & 3) * 2;
        bv0[ni] = __ldg(bias + f);
        bv1[ni] = __ldg(bias + f + 1);
    }

    // ---- build slab for first job (6 rows) ----
    {
        int bz0 = jstart >> 4;
        int ht0 = jstart & 15;
        build_rows(x + (size_t)bz0 * Cn * Hn * Wn, smem_raw, tid, 4 * ht0, 6);
    }
    asm volatile("cp.async.wait_group 0;");        // resident weights done

    #pragma unroll 1
    for (int jj = 0; jj < jcount; jj++) {
        const int j  = jstart + jj;
        const int bz = j >> 4;
        const int ht = j & 15;
        const int h0 = 4 * ht;
        const int ghw = h0 + wm;                    // warp's output row

        __syncthreads();               // slab (+weights on 1st job) visible

        // stream this job's taps 6,7 (consumed far later)
        stream_tap(sb + SBUF0, gsrc6, tid);
        stream_tap(sb + SBUF1, gsrc7, tid);

        float acc[4][4][4];            // [mi(w16)][ni(f8)][quad] = 64 regs
        #pragma unroll
        for (int mi = 0; mi < 4; mi++)
            #pragma unroll
            for (int ni = 0; ni < 4; ni++)
                #pragma unroll
                for (int q = 0; q < 4; q++) acc[mi][ni][q] = 0.0f;

        uint32_t Af[2][4][4], Bf[2][2][4];

        // ---- pipelined segment: taps 0..5 (resident) ----
        {
            const int sb00 = (ghw % 6) * 64 + arow;              // t0: ki=0,kj=0
            LOAD_STEP(0, sb + (uint32_t)sb00 * 128,
                      (uint32_t)(sb00 & 7) << 4, wres, 0u);
        }
        #pragma unroll 1
        for (int t = 0; t < 6; t++) {
            const int ki = t / 3;
            const int kj = t - 3 * ki;
            const int sbase = ((ghw + ki) % 6) * 64 + arow + kj;
            const uint32_t swzA  = (uint32_t)(sbase & 7) << 4;
            const uint32_t aBase = sb + (uint32_t)sbase * 128;
            const uint32_t bTap  = wres + (uint32_t)t * 8192;

            const int tn  = (t < 5) ? t + 1 : 5;                 // t=5: dummy self
            const int nki = tn / 3;
            const int nkj = tn - 3 * nki;
            const int nsb = ((ghw + nki) % 6) * 64 + arow + nkj;
            const uint32_t nswzA  = (uint32_t)(nsb & 7) << 4;
            const uint32_t naBase = sb + (uint32_t)nsb * 128;
            const uint32_t nbTap  = wres + (uint32_t)tn * 8192;

            // kc = 0 (cur buf0): prefetch kc1 -> buf1
            LOAD_STEP(1, aBase, swzA, bTap, 32u);
            MMA_STEP(0);
            // kc = 1: prefetch kc2 -> buf0
            LOAD_STEP(0, aBase, swzA, bTap, 64u);
            MMA_STEP(1);
            // kc = 2: prefetch kc3 -> buf1
            LOAD_STEP(1, aBase, swzA, bTap, 96u);
            MMA_STEP(0);
            // kc = 3: prefetch next tap kc0 -> buf0
            LOAD_STEP(0, naBase, nswzA, nbTap, 0u);
            MMA_STEP(1);
        }

        // ---- streamed taps 6,7,8 ----
        #pragma unroll 1
        for (int t = 6; t < 9; t++) {
            if (t == 8) {
                __syncthreads();                       // everyone done with buf0(t6)
                stream_tap(sb + SBUF0, gsrc8, tid);    // t8 -> buf0
            }
            asm volatile("cp.async.wait_group 1;");    // this tap's data done
            if (t == 8) asm volatile("cp.async.wait_group 0;");
            __syncthreads();                           // cross-thread visibility

            const int ki = t / 3;
            const int kj = t - 3 * ki;
            const int sbase = ((ghw + ki) % 6) * 64 + arow + kj;
            const uint32_t swzA  = (uint32_t)(sbase & 7) << 4;
            const uint32_t aBase = sb + (uint32_t)sbase * 128;
            const uint32_t bTap  = (t == 7) ? sbuf1 : sbuf0;

            LOAD_STEP(0, aBase, swzA, bTap, 0u);       // preamble (bubble)
            LOAD_STEP(1, aBase, swzA, bTap, 32u);
            MMA_STEP(0);
            LOAD_STEP(0, aBase, swzA, bTap, 64u);
            MMA_STEP(1);
            LOAD_STEP(1, aBase, swzA, bTap, 96u);
            MMA_STEP(0);
            MMA_STEP(1);
        }

        __syncthreads();               // all reads done; ring + bufs reusable

        // ---- build slab rows for next job (overlaps epilogue) ----
        if (jj + 1 < jcount) {
            const int nj  = j + 1;
            const int nbz = nj >> 4;
            const int nht = nj & 15;
            const float* nxb = x + (size_t)nbz * Cn * Hn * Wn;
            if (nht != 0) build_rows(nxb, smem_raw, tid, 4 * nht + 2, 4);
            else          build_rows(nxb, smem_raw, tid, 0, 6);
        }

        // ---- epilogue: acc -> out[bz, f, oh, ow] + bias ----
        const int oh = ghw;
        if (oh < HOn) {
            #pragma unroll
            for (int ni = 0; ni < 4; ni++) {
                const int f = fh * 64 + wn * 32 + ni * 8 + (lane & 3) * 2;
                float* p0 = out + (((size_t)bz * Fn + f) * HOn + oh) * WOn;
                float* p1 = p0 + (size_t)HOn * WOn;
                #pragma unroll
                for (int mi = 0; mi < 4; mi++) {
                    const int w0 = mi * 16 + (lane >> 2);   // <= 55
                    const int w1 = w0 + 8;
                    p0[w0] = acc[mi][ni][0] + bv0[ni];
                    p1[w0] = acc[mi][ni][1] + bv1[ni];
                    if (w1 < WOn) {
                        p0[w1] = acc[mi][ni][2] + bv0[ni];
                        p1[w1] = acc[mi][ni][3] + bv1[ni];
                    }
                }
            }
        }
    }
}

extern "C" void kernel_launch(void* const* d_in, const int* in_sizes, int n_in,
                              void* d_out, int out_size) {
    const float* x    = (const float*)d_in[0];   // (32,64,64,64)
    const float* k1   = (const float*)d_in[1];   // (3,3,64,128)
    const float* k2   = (const float*)d_in[2];   // (3,3,64,128)
    const float* bias = (const float*)d_in[3];   // (128,)
    float* out = (float*)d_out;                  // (32,128,62,62)
    (void)in_sizes; (void)n_in; (void)out_size;

    cudaFuncSetAttribute(conv_hmma_kernel,
                         cudaFuncAttributeMaxDynamicSharedMemorySize, SMEM_TOTAL);

    prep_w<<<288, 256>>>(k1, k2);
    dim3 grid(2, NCTA_PER_HALF);       // 296 CTAs, 2/SM, one wave
    conv_hmma_kernel<<<grid, 256, SMEM_TOTAL>>>(x, bias, out);
}

// round 13
// speedup vs baseline: 1.0095x; 1.0095x over previous
#include <cuda_runtime.h>
#include <cuda_fp16.h>
#include <cstdint>

// MorphLayer == conv2d(x, exp(k1)-exp(k2), VALID 3x3) + bias  (exact reduction)
// B=32 C=64 H=W=64 -> Ho=Wo=62, F=128.
// HMMA implicit-GEMM, single fp16 product, fp32 acc.
// R13 = R11 (best, 66us) + x pre-transposed to fp16 [bz][h][w][c] 128B rows,
// PRE-SWIZZLED (XOR pattern depends only on gw&7, valid for any ring slot):
// main-kernel slab build becomes pure contiguous cp.async copies.

#define Hn  64
#define Wn  64
#define HOn 62
#define WOn 62
#define Fn  128
#define Cn  64

#define SLAB_ROWS  258                     // 4 ring slots * 64 + 2 pad rows
#define SLAB_BYTES (SLAB_ROWS * 128)       // 33024
#define WOFF       SLAB_BYTES
#define WRES_BYTES (9 * 64 * 128)          // 73728
#define SMEM_TOTAL (WOFF + WRES_BYTES)     // 106752 -> 2 CTAs/SM

#define JOBS_PER_HALF 992                  // 31 h-tiles * 32 batch
#define NCTA_PER_HALF 148
#define JOBS_PER_CTA  7

// fp16 weights, SW128-swizzled: [tap][f=128][c=64]
__device__ __align__(16) unsigned char g_W[9 * 16384];
// fp16 x, transposed + per-row swizzled: [bz][h][w] -> 128B row of 64 c
__device__ __align__(16) unsigned char g_xT[32 * 64 * 64 * 128];

__device__ __forceinline__ uint32_t smem_u32(const void* p) {
    uint32_t a;
    asm("{ .reg .u64 t; cvta.to.shared.u64 t, %1; cvt.u32.u64 %0, t; }" : "=r"(a) : "l"(p));
    return a;
}

#define LDSM4(r, addr)                                                          \
    asm volatile("ldmatrix.sync.aligned.m8n8.x4.shared.b16 {%0,%1,%2,%3}, [%4];" \
                 : "=r"((r)[0]), "=r"((r)[1]), "=r"((r)[2]), "=r"((r)[3])        \
                 : "r"(addr))

#define MMA(d, a, b0, b1)                                                       \
    asm volatile("mma.sync.aligned.m16n8k16.row.col.f32.f16.f16.f32 "           \
                 "{%0,%1,%2,%3}, {%4,%5,%6,%7}, {%8,%9}, {%0,%1,%2,%3};"        \
                 : "+f"((d)[0]), "+f"((d)[1]), "+f"((d)[2]), "+f"((d)[3])        \
                 : "r"((a)[0]), "r"((a)[1]), "r"((a)[2]), "r"((a)[3]),           \
                   "r"(b0), "r"(b1))

// ---------------- weight prep ----------------
__global__ void prep_w(const float* __restrict__ k1, const float* __restrict__ k2) {
    int idx = blockIdx.x * 256 + threadIdx.x;       // 73728 = 9*128*64
    int t   = idx >> 13;
    int rem = idx & 8191;
    int f   = rem >> 6;
    int c   = rem & 63;
    int src = (t * 64 + c) * 128 + f;               // k1 layout (kh,kw,C,F)
    float w = expf(k1[src]) - expf(k2[src]);
    __half h = __float2half_rn(w);
    unsigned off = (unsigned)(f * 128 + c * 2);
    off = off ^ ((off >> 3) & 0x70);                // SW128 swizzle
    *(unsigned short*)(g_W + t * 16384 + off) = *(unsigned short*)&h;
}

// ---------------- x prep: fp32 [bz][c][h][w] -> fp16 [bz][h][w][c] swizzled ----
__global__ void prep_x(const float* __restrict__ x) {
    __shared__ float tile[64][65];
    const int h  = blockIdx.x;
    const int bz = blockIdx.y;
    const int tid = threadIdx.x;
    #pragma unroll
    for (int i = 0; i < 16; i++) {
        int idx = tid + i * 256;
        int c = idx >> 6;
        int w = idx & 63;
        tile[c][w] = x[(((size_t)bz * 64 + c) * 64 + h) * 64 + w];
    }
    __syncthreads();
    unsigned char* dst = g_xT + (((size_t)bz * 64 + h) * 64) * 128;
    #pragma unroll
    for (int i = 0; i < 2; i++) {
        int t  = tid + i * 256;
        int w  = t >> 3;
        int cg = t & 7;
        unsigned short hs[8];
        #pragma unroll
        for (int k = 0; k < 8; k++) {
            __half hv = __float2half_rn(tile[cg * 8 + k][w]);
            hs[k] = *(unsigned short*)&hv;
        }
        unsigned off = (unsigned)(w * 128) + (((unsigned)cg * 16) ^ (((unsigned)w & 7) << 4));
        *(uint4*)(dst + off) =
            make_uint4((uint32_t)hs[0] | ((uint32_t)hs[1] << 16),
                       (uint32_t)hs[2] | ((uint32_t)hs[3] << 16),
                       (uint32_t)hs[4] | ((uint32_t)hs[5] << 16),
                       (uint32_t)hs[6] | ((uint32_t)hs[7] << 16));
    }
}

// ---------------- main kernel ----------------
extern __shared__ char smem_raw[];

// pure async copy: slab rows gh0..gh0+nrows-1 (pre-swizzled 128B rows)
__device__ __forceinline__ void build_rows_async(const unsigned char* __restrict__ xTb,
                                                 uint32_t sbs, int tid,
                                                 int gh0, int nrows) {
    const int total = nrows * 512;              // 16B chunks
    #pragma unroll
    for (int t = tid; t < total; t += 256) {
        int chunk = t & 7;
        int gw    = (t >> 3) & 63;
        int gh    = gh0 + (t >> 9);
        const unsigned char* src = xTb + ((size_t)gh * 64 + gw) * 128 + chunk * 16;
        uint32_t dst = sbs + (uint32_t)((((gh & 3) * 64 + gw) * 128) + chunk * 16);
        asm volatile("cp.async.cg.shared.global [%0], [%1], 16;"
                     :: "r"(dst), "l"(src));
    }
    asm volatile("cp.async.commit_group;");
}

__global__ void __launch_bounds__(256, 2)
conv_hmma_kernel(const float* __restrict__ bias,
                 float* __restrict__ out) {
    const int tid  = threadIdx.x;
    const int lane = tid & 31;
    const int wid  = tid >> 5;
    const int wm   = wid & 3;          // M block: oh = wm>>1, w-half = wm&1
    const int wn   = wid >> 2;         // N block: 32 filters
    const int fh   = blockIdx.x;       // filter half
    const int cid  = blockIdx.y;

    const int jstart = cid * JOBS_PER_CTA;
    if (jstart >= JOBS_PER_HALF) return;
    const int jend = (jstart + JOBS_PER_CTA < JOBS_PER_HALF)
                   ? jstart + JOBS_PER_CTA : JOBS_PER_HALF;

    const uint32_t sb = smem_u32(smem_raw);

    // ---- resident weight load: 64 filters x 9 taps (72KB), once per CTA ----
    {
        const unsigned char* src = g_W + fh * 8192;
        #pragma unroll
        for (int j = 0; j < 18; j++) {
            int k = tid + j * 256;
            int tap = k >> 9;
            int rem = k & 511;
            asm volatile("cp.async.cg.shared.global [%0], [%1], 16;"
                         :: "r"(sb + WOFF + (uint32_t)k * 16),
                            "l"(src + (size_t)tap * 16384 + rem * 16));
        }
        asm volatile("cp.async.commit_group;");
    }

    // zero pad rows 256..257 (feeds only discarded outputs)
    if (tid < 16) {
        *(uint4*)(smem_raw + 256 * 128 + tid * 16) = make_uint4(0u, 0u, 0u, 0u);
    }

    // lane-constant addressing
    const int      a_lrow  = lane & 15;
    const uint32_t a_hi16  = (uint32_t)(lane >> 4) * 16;
    const int      fb0     = wn * 32 + (lane & 7) + ((lane >> 4) & 1) * 8;
    const uint32_t b_off16 = (uint32_t)((lane >> 3) & 1) * 16;
    const uint32_t swzB    = (uint32_t)(fb0 & 7) << 4;
    const uint32_t wBase   = sb + WOFF + (uint32_t)fb0 * 128;
    const int      mrow0   = (wm & 1) * 32 + a_lrow;

    // bias hoisted
    float bv0[4], bv1[4];
    #pragma unroll
    for (int ni = 0; ni < 4; ni++) {
        const int f = fh * 64 + wn * 32 + ni * 8 + (lane & 3) * 2;
        bv0[ni] = __ldg(bias + f);
        bv1[ni] = __ldg(bias + f + 1);
    }

    // ---- build slab for first job (4 rows, async) ----
    int j0bz = jstart / 31;
    int j0ht = jstart - j0bz * 31;
    build_rows_async(g_xT + (size_t)j0bz * 64 * 64 * 128, sb, tid, 2 * j0ht, 4);
    asm volatile("cp.async.wait_group 0;");     // weights + first slab

    #pragma unroll 1
    for (int j = jstart; j < jend; j++) {
        const int bz = j / 31;
        const int ht = j - bz * 31;
        const int h0 = 2 * ht;

        asm volatile("cp.async.wait_group 0;"); // slab copies landed
        __syncthreads();                        // visible to all warps

        float acc[2][4][4];
        #pragma unroll
        for (int mi = 0; mi < 2; mi++)
            #pragma unroll
            for (int ni = 0; ni < 4; ni++)
                #pragma unroll
                for (int q = 0; q < 4; q++) acc[mi][ni][q] = 0.0f;

        // fragment double buffers (index = kc&1, statically resolved)
        uint32_t Af[2][2][4], Bf[2][2][4];

        // preamble: load step (t=0, kc=0) into buf 0
        {
            const int sbase = ((h0 + (wm >> 1)) & 3) * 64 + mrow0;   // ki=0,kj=0
            const uint32_t swzA  = (uint32_t)(sbase & 7) << 4;
            const uint32_t aB    = sb + (uint32_t)sbase * 128;
            const uint32_t aoff  = a_hi16 ^ swzA;
            const uint32_t boff  = b_off16 ^ swzB;
            LDSM4(Af[0][0], aB + aoff);
            LDSM4(Af[0][1], aB + 2048 + aoff);
            LDSM4(Bf[0][0], wBase + boff);
            LDSM4(Bf[0][1], wBase + 2048 + boff);
        }

        #pragma unroll 1
        for (int t = 0; t < 9; t++) {
            const int ki = t / 3;
            const int kj = t - 3 * ki;
            const int sbase = ((h0 + (wm >> 1) + ki) & 3) * 64 + mrow0 + kj;
            const uint32_t swzA  = (uint32_t)(sbase & 7) << 4;
            const uint32_t aBase = sb + (uint32_t)sbase * 128;
            const uint32_t bTap  = wBase + (uint32_t)t * 8192;

            const int tn  = (t < 8) ? t + 1 : 8;     // t=8: dummy self
            const int nki = tn / 3;
            const int nkj = tn - 3 * nki;
            const int nsb = ((h0 + (wm >> 1) + nki) & 3) * 64 + mrow0 + nkj;
            const uint32_t nswzA  = (uint32_t)(nsb & 7) << 4;
            const uint32_t naBase = sb + (uint32_t)nsb * 128;
            const uint32_t nbTap  = wBase + (uint32_t)tn * 8192;

            #pragma unroll
            for (int kc = 0; kc < 4; kc++) {
                const int cur = kc & 1;
                const int nxt = cur ^ 1;
                const uint32_t pa   = (kc < 3) ? aBase : naBase;
                const uint32_t pb   = (kc < 3) ? bTap  : nbTap;
                const uint32_t pswz = (kc < 3) ? swzA  : nswzA;
                const uint32_t pkc  = (kc < 3) ? (uint32_t)((kc + 1) * 32) : 0u;
                const uint32_t aoffn = (pkc + a_hi16) ^ pswz;
                const uint32_t boffn = (pkc + b_off16) ^ swzB;
                LDSM4(Af[nxt][0], pa + aoffn);
                LDSM4(Af[nxt][1], pa + 2048 + aoffn);
                LDSM4(Bf[nxt][0], pb + boffn);
                LDSM4(Bf[nxt][1], pb + 2048 + boffn);

                #pragma unroll
                for (int mi = 0; mi < 2; mi++)
                    #pragma unroll
                    for (int bi = 0; bi < 2; bi++) {
                        MMA(acc[mi][2 * bi],     Af[cur][mi], Bf[cur][bi][0], Bf[cur][bi][1]);
                        MMA(acc[mi][2 * bi + 1], Af[cur][mi], Bf[cur][bi][2], Bf[cur][bi][3]);
                    }
            }
        }

        __syncthreads();               // all reads done; slab slots reusable

        // ---- async build for next job (overlaps epilogue + next-job wait) ----
        if (j + 1 < jend) {
            const int nbz = (j + 1) / 31;
            const int nht = (j + 1) - nbz * 31;
            const unsigned char* nxT = g_xT + (size_t)nbz * 64 * 64 * 128;
            if (nht != 0) build_rows_async(nxT, sb, tid, 2 * nht + 2, 2);
            else          build_rows_async(nxT, sb, tid, 0, 4);
        }

        // ---- epilogue ----
        const int oh  = h0 + (wm >> 1);
        const int wpx = (wm & 1) * 32;
        #pragma unroll
        for (int ni = 0; ni < 4; ni++) {
            const int f = fh * 64 + wn * 32 + ni * 8 + (lane & 3) * 2;
            float* p0 = out + (((size_t)bz * Fn + f) * HOn + oh) * WOn;
            float* p1 = p0 + (size_t)HOn * WOn;
            #pragma unroll
            for (int mi = 0; mi < 2; mi++) {
                const int w0 = wpx + mi * 16 + (lane >> 2);
                const int w1 = w0 + 8;
                p0[w0] = acc[mi][ni][0] + bv0[ni];
                p1[w0] = acc[mi][ni][1] + bv1[ni];
                if (w1 < WOn) {
                    p0[w1] = acc[mi][ni][2] + bv0[ni];
                    p1[w1] = acc[mi][ni][3] + bv1[ni];
                }
            }
        }
    }
}

extern "C" void kernel_launch(void* const* d_in, const int* in_sizes, int n_in,
                              void* d_out, int out_size) {
    const float* x    = (const float*)d_in[0];   // (32,64,64,64)
    const float* k1   = (const float*)d_in[1];   // (3,3,64,128)
    const float* k2   = (const float*)d_in[2];   // (3,3,64,128)
    const float* bias = (const float*)d_in[3];   // (128,)
    float* out = (float*)d_out;                  // (32,128,62,62)
    (void)in_sizes; (void)n_in; (void)out_size;

    cudaFuncSetAttribute(conv_hmma_kernel,
                         cudaFuncAttributeMaxDynamicSharedMemorySize, SMEM_TOTAL);

    prep_w<<<288, 256>>>(k1, k2);
    prep_x<<<dim3(64, 32), 256>>>(x);
    dim3 grid(2, NCTA_PER_HALF);       // 296 CTAs, 2/SM, one wave
    conv_hmma_kernel<<<grid, 256, SMEM_TOTAL>>>(bias, out);
}

// round 14
// speedup vs baseline: 1.0437x; 1.0338x over previous
#include <cuda_runtime.h>
#include <cuda_fp16.h>
#include <cstdint>

// MorphLayer == conv2d(x, exp(k1)-exp(k2), VALID 3x3) + bias  (exact reduction)
// B=32 C=64 H=W=64 -> Ho=Wo=62, F=128.
// HMMA implicit-GEMM, single fp16 product, fp32 acc.
// R14 = R13 main (R11 pipeline + pre-transposed g_xT + pure cp.async slab)
//  + SWAPPED MMA operands: A = W (m16 rows = filters), B = x (n8 cols = ow)
//    -> accumulator quads are consecutive-ow pairs -> STG.64 epilogue
//  + prep_w and prep_x merged into ONE launch (independent work, one grid).

#define Hn  64
#define Wn  64
#define HOn 62
#define WOn 62
#define Fn  128
#define Cn  64

#define SLAB_ROWS  258                     // 4 ring slots * 64 + 2 pad rows
#define SLAB_BYTES (SLAB_ROWS * 128)       // 33024
#define WOFF       SLAB_BYTES
#define WRES_BYTES (9 * 64 * 128)          // 73728
#define SMEM_TOTAL (WOFF + WRES_BYTES)     // 106752 -> 2 CTAs/SM

#define JOBS_PER_HALF 992                  // 31 h-tiles * 32 batch
#define NCTA_PER_HALF 148
#define JOBS_PER_CTA  7

// fp16 weights, SW128-swizzled: [tap][f=128][c=64]
__device__ __align__(16) unsigned char g_W[9 * 16384];
// fp16 x, transposed + per-row swizzled: [bz][h][w] -> 128B row of 64 c
__device__ __align__(16) unsigned char g_xT[32 * 64 * 64 * 128];

__device__ __forceinline__ uint32_t smem_u32(const void* p) {
    uint32_t a;
    asm("{ .reg .u64 t; cvta.to.shared.u64 t, %1; cvt.u32.u64 %0, t; }" : "=r"(a) : "l"(p));
    return a;
}

#define LDSM4(r, addr)                                                          \
    asm volatile("ldmatrix.sync.aligned.m8n8.x4.shared.b16 {%0,%1,%2,%3}, [%4];" \
                 : "=r"((r)[0]), "=r"((r)[1]), "=r"((r)[2]), "=r"((r)[3])        \
                 : "r"(addr))

#define MMA(d, a, b0, b1)                                                       \
    asm volatile("mma.sync.aligned.m16n8k16.row.col.f32.f16.f16.f32 "           \
                 "{%0,%1,%2,%3}, {%4,%5,%6,%7}, {%8,%9}, {%0,%1,%2,%3};"        \
                 : "+f"((d)[0]), "+f"((d)[1]), "+f"((d)[2]), "+f"((d)[3])        \
                 : "r"((a)[0]), "r"((a)[1]), "r"((a)[2]), "r"((a)[3]),           \
                   "r"(b0), "r"(b1))

// ---------------- combined prep: weights + x transpose in ONE launch ----------
__global__ void prep_all(const float* __restrict__ k1, const float* __restrict__ k2,
                         const float* __restrict__ x) {
    const int tid = threadIdx.x;
    if (blockIdx.x < 288) {
        // ---- W part: w = exp(k1)-exp(k2) -> fp16, swizzled [tap][f][c] ----
        int idx = blockIdx.x * 256 + tid;           // 73728 = 9*128*64
        int t   = idx >> 13;
        int rem = idx & 8191;
        int f   = rem >> 6;
        int c   = rem & 63;
        int src = (t * 64 + c) * 128 + f;           // k1 layout (kh,kw,C,F)
        float w = expf(k1[src]) - expf(k2[src]);
        __half h = __float2half_rn(w);
        unsigned off = (unsigned)(f * 128 + c * 2);
        off = off ^ ((off >> 3) & 0x70);            // SW128 swizzle
        *(unsigned short*)(g_W + t * 16384 + off) = *(unsigned short*)&h;
    } else {
        // ---- x part: fp32 [bz][c][h][w] -> fp16 [bz][h][w][c] swizzled ----
        __shared__ float tile[64][65];
        const int b  = blockIdx.x - 288;            // 2048 blocks
        const int h  = b & 63;
        const int bz = b >> 6;
        #pragma unroll
        for (int i = 0; i < 16; i++) {
            int idx = tid + i * 256;
            int c = idx >> 6;
            int w = idx & 63;
            tile[c][w] = x[(((size_t)bz * 64 + c) * 64 + h) * 64 + w];
        }
        __syncthreads();
        unsigned char* dst = g_xT + (((size_t)bz * 64 + h) * 64) * 128;
        #pragma unroll
        for (int i = 0; i < 2; i++) {
            int t  = tid + i * 256;
            int w  = t >> 3;
            int cg = t & 7;
            unsigned short hs[8];
            #pragma unroll
            for (int k = 0; k < 8; k++) {
                __half hv = __float2half_rn(tile[cg * 8 + k][w]);
                hs[k] = *(unsigned short*)&hv;
            }
            unsigned off = (unsigned)(w * 128)
                         + (((unsigned)cg * 16) ^ (((unsigned)w & 7) << 4));
            *(uint4*)(dst + off) =
                make_uint4((uint32_t)hs[0] | ((uint32_t)hs[1] << 16),
                           (uint32_t)hs[2] | ((uint32_t)hs[3] << 16),
                           (uint32_t)hs[4] | ((uint32_t)hs[5] << 16),
                           (uint32_t)hs[6] | ((uint32_t)hs[7] << 16));
        }
    }
}

// ---------------- main kernel ----------------
extern __shared__ char smem_raw[];

// pure async copy: slab rows gh0..gh0+nrows-1 (pre-swizzled 128B rows)
__device__ __forceinline__ void build_rows_async(const unsigned char* __restrict__ xTb,
                                                 uint32_t sbs, int tid,
                                                 int gh0, int nrows) {
    const int total = nrows * 512;              // 16B chunks
    #pragma unroll
    for (int t = tid; t < total; t += 256) {
        int chunk = t & 7;
        int gw    = (t >> 3) & 63;
        int gh    = gh0 + (t >> 9);
        const unsigned char* src = xTb + ((size_t)gh * 64 + gw) * 128 + chunk * 16;
        uint32_t dst = sbs + (uint32_t)((((gh & 3) * 64 + gw) * 128) + chunk * 16);
        asm volatile("cp.async.cg.shared.global [%0], [%1], 16;"
                     :: "r"(dst), "l"(src));
    }
    asm volatile("cp.async.commit_group;");
}

__global__ void __launch_bounds__(256, 2)
conv_hmma_kernel(const float* __restrict__ bias,
                 float* __restrict__ out) {
    const int tid  = threadIdx.x;
    const int lane = tid & 31;
    const int wid  = tid >> 5;
    const int wm   = wid & 3;          // M block: oh = wm>>1, w-half = wm&1
    const int wn   = wid >> 2;         // N block: 32 filters
    const int fh   = blockIdx.x;       // filter half
    const int cid  = blockIdx.y;

    const int jstart = cid * JOBS_PER_CTA;
    if (jstart >= JOBS_PER_HALF) return;
    const int jend = (jstart + JOBS_PER_CTA < JOBS_PER_HALF)
                   ? jstart + JOBS_PER_CTA : JOBS_PER_HALF;

    const uint32_t sb = smem_u32(smem_raw);

    // ---- resident weight load: 64 filters x 9 taps (72KB), once per CTA ----
    {
        const unsigned char* src = g_W + fh * 8192;
        #pragma unroll
        for (int j = 0; j < 18; j++) {
            int k = tid + j * 256;
            int tap = k >> 9;
            int rem = k & 511;
            asm volatile("cp.async.cg.shared.global [%0], [%1], 16;"
                         :: "r"(sb + WOFF + (uint32_t)k * 16),
                            "l"(src + (size_t)tap * 16384 + rem * 16));
        }
        asm volatile("cp.async.commit_group;");
    }

    // zero pad rows 256..257 (overflow target; feeds only discarded outputs)
    if (tid < 16) {
        *(uint4*)(smem_raw + 256 * 128 + tid * 16) = make_uint4(0u, 0u, 0u, 0u);
    }

    // ---- lane-constant addressing (operands SWAPPED: A = W, B = x) ----
    // A (W): m16 rows = filters; k-contiguous rows, constant swizzle per lane
    const uint32_t a_hi16 = (uint32_t)(lane >> 4) * 16;            // k half
    const uint32_t swzAW  = (uint32_t)(lane & 7) << 4;
    const uint32_t wA     = sb + WOFF + (uint32_t)(wn * 32 + (lane & 15)) * 128;
    // B (x): n8 cols = ow; rows = spatial slab rows
    const int      wb0    = (wm & 1) * 32 + (lane & 7) + ((lane >> 4) & 1) * 8;
    const uint32_t bk16   = (uint32_t)((lane >> 3) & 1) * 16;      // k half

    // bias hoisted: f = fh*64 + wn*32 + mi*16 + (lane>>2) + half*8
    const int fb = fh * 64 + wn * 32 + (lane >> 2);
    float bv[2][2];
    #pragma unroll
    for (int mi = 0; mi < 2; mi++)
        #pragma unroll
        for (int hf = 0; hf < 2; hf++)
            bv[mi][hf] = __ldg(bias + fb + mi * 16 + hf * 8);

    // ---- build slab for first job (4 rows, async) ----
    int j0bz = jstart / 31;
    int j0ht = jstart - j0bz * 31;
    build_rows_async(g_xT + (size_t)j0bz * 64 * 64 * 128, sb, tid, 2 * j0ht, 4);

    #pragma unroll 1
    for (int j = jstart; j < jend; j++) {
        const int bz = j / 31;
        const int ht = j - bz * 31;
        const int h0 = 2 * ht;

        asm volatile("cp.async.wait_group 0;"); // weights + slab copies landed
        __syncthreads();                        // visible to all warps

        float acc[2][4][4];                     // [mi(f16)][ni(ow8)][quad]
        #pragma unroll
        for (int mi = 0; mi < 2; mi++)
            #pragma unroll
            for (int ni = 0; ni < 4; ni++)
                #pragma unroll
                for (int q = 0; q < 4; q++) acc[mi][ni][q] = 0.0f;

        // fragment double buffers (index = kc&1, statically resolved)
        uint32_t Af[2][2][4], Bf[2][2][4];

        // preamble: load step (t=0, kc=0) into buf 0
        {
            const int xrow = ((h0 + (wm >> 1)) & 3) * 64 + wb0;     // ki=0,kj=0
            const uint32_t swzB = (uint32_t)(lane & 7) << 4;
            const uint32_t bB   = sb + (uint32_t)xrow * 128;
            const uint32_t aoff = a_hi16 ^ swzAW;
            const uint32_t boff = bk16 ^ swzB;
            LDSM4(Af[0][0], wA + aoff);
            LDSM4(Af[0][1], wA + 2048 + aoff);
            LDSM4(Bf[0][0], bB + boff);
            LDSM4(Bf[0][1], bB + 2048 + boff);
        }

        #pragma unroll 1
        for (int t = 0; t < 9; t++) {
            const int ki = t / 3;
            const int kj = t - 3 * ki;
            const int xrow = ((h0 + (wm >> 1) + ki) & 3) * 64 + wb0 + kj;
            const uint32_t swzB  = (uint32_t)(((lane & 7) + kj) & 7) << 4;
            const uint32_t bBase = sb + (uint32_t)xrow * 128;
            const uint32_t aBase = wA + (uint32_t)t * 8192;

            const int tn  = (t < 8) ? t + 1 : 8;     // t=8: dummy self
            const int nki = tn / 3;
            const int nkj = tn - 3 * nki;
            const int nxr = ((h0 + (wm >> 1) + nki) & 3) * 64 + wb0 + nkj;
            const uint32_t nswzB  = (uint32_t)(((lane & 7) + nkj) & 7) << 4;
            const uint32_t nbBase = sb + (uint32_t)nxr * 128;
            const uint32_t naBase = wA + (uint32_t)tn * 8192;

            #pragma unroll
            for (int kc = 0; kc < 4; kc++) {
                const int cur = kc & 1;
                const int nxt = cur ^ 1;
                const uint32_t pa   = (kc < 3) ? aBase : naBase;
                const uint32_t pb   = (kc < 3) ? bBase : nbBase;
                const uint32_t pswz = (kc < 3) ? swzB  : nswzB;
                const uint32_t pkc  = (kc < 3) ? (uint32_t)((kc + 1) * 32) : 0u;
                const uint32_t aoffn = (pkc + a_hi16) ^ swzAW;
                const uint32_t boffn = (pkc + bk16) ^ pswz;
                LDSM4(Af[nxt][0], pa + aoffn);
                LDSM4(Af[nxt][1], pa + 2048 + aoffn);
                LDSM4(Bf[nxt][0], pb + boffn);
                LDSM4(Bf[nxt][1], pb + 2048 + boffn);

                #pragma unroll
                for (int mi = 0; mi < 2; mi++)
                    #pragma unroll
                    for (int wi = 0; wi < 2; wi++) {
                        MMA(acc[mi][2 * wi],     Af[cur][mi], Bf[cur][wi][0], Bf[cur][wi][1]);
                        MMA(acc[mi][2 * wi + 1], Af[cur][mi], Bf[cur][wi][2], Bf[cur][wi][3]);
                    }
            }
        }

        __syncthreads();               // all reads done; slab slots reusable

        // ---- async build for next job (overlaps epilogue) ----
        if (j + 1 < jend) {
            const int nbz = (j + 1) / 31;
            const int nht = (j + 1) - nbz * 31;
            const unsigned char* nxT = g_xT + (size_t)nbz * 64 * 64 * 128;
            if (nht != 0) build_rows_async(nxT, sb, tid, 2 * nht + 2, 2);
            else          build_rows_async(nxT, sb, tid, 0, 4);
        }

        // ---- epilogue: STG.64 of consecutive-ow pairs ----
        const int oh  = h0 + (wm >> 1);
        const int wpx = (wm & 1) * 32;
        #pragma unroll
        for (int mi = 0; mi < 2; mi++) {
            const int f0 = fb + mi * 16;
            float* p0 = out + (((size_t)bz * Fn + f0) * HOn + oh) * WOn;
            float* p1 = p0 + (size_t)8 * HOn * WOn;     // f0 + 8
            #pragma unroll
            for (int ni = 0; ni < 4; ni++) {
                const int ow = wpx + ni * 8 + (lane & 3) * 2;
                if (ow < WOn) {       // pair (62,63) dropped whole
                    float2 v0 = make_float2(acc[mi][ni][0] + bv[mi][0],
                                            acc[mi][ni][1] + bv[mi][0]);
                    float2 v1 = make_float2(acc[mi][ni][2] + bv[mi][1],
                                            acc[mi][ni][3] + bv[mi][1]);
                    *(float2*)(p0 + ow) = v0;
                    *(float2*)(p1 + ow) = v1;
                }
            }
        }
    }
}

extern "C" void kernel_launch(void* const* d_in, const int* in_sizes, int n_in,
                              void* d_out, int out_size) {
    const float* x    = (const float*)d_in[0];   // (32,64,64,64)
    const float* k1   = (const float*)d_in[1];   // (3,3,64,128)
    const float* k2   = (const float*)d_in[2];   // (3,3,64,128)
    const float* bias = (const float*)d_in[3];   // (128,)
    float* out = (float*)d_out;                  // (32,128,62,62)
    (void)in_sizes; (void)n_in; (void)out_size;

    cudaFuncSetAttribute(conv_hmma_kernel,
                         cudaFuncAttributeMaxDynamicSharedMemorySize, SMEM_TOTAL);

    prep_all<<<288 + 2048, 256>>>(k1, k2, x);    // one merged prep launch
    dim3 grid(2, NCTA_PER_HALF);                 // 296 CTAs, 2/SM, one wave
    conv_hmma_kernel<<<grid, 256, SMEM_TOTAL>>>(bias, out);
}